// round 2
// baseline (speedup 1.0000x reference)
#include <cuda_runtime.h>
#include <cuda_bf16.h>

// MLLoss: per-sample hinge loss over [B, 16] distances, reduced to scalar mean.
// NOTE: labels come from JAX with x64 disabled -> they are int32, not int64.
//
// loss_control   = d0 + hinge_sum - h0          (doctor == 0)
// loss_parkinson = d1 + hinge_sum - h1          (doctor == 1)
// loss_unknown   = real==0 ? h1 : h0            (doctor == 2, real in {0,1})
// out = sum(per_sample) / B
//
// HBM-bound: 288 MB read. float4 x4 per row, branch-free math,
// warp+block reduction, one float atomicAdd per block (pre-scaled by 1/B).

#define THREADS 256

__global__ void zero_out_kernel(float* __restrict__ out) {
    if (threadIdx.x == 0) out[0] = 0.0f;
}

__global__ __launch_bounds__(THREADS)
void mlloss_kernel(const float4* __restrict__ dist4,  // B*4 float4 = [B,16] f32
                   const int* __restrict__ doctor,    // [B] int32 in {0,1,2}
                   const int* __restrict__ real_l,    // [B] int32 in {0,1}
                   float* __restrict__ out,
                   int B, float inv_B)
{
    const int tid    = blockIdx.x * blockDim.x + threadIdx.x;
    const int stride = gridDim.x * blockDim.x;

    float acc = 0.0f;

    for (int row = tid; row < B; row += stride) {
        const float4 a = dist4[(size_t)row * 4 + 0];
        const float4 b = dist4[(size_t)row * 4 + 1];
        const float4 c = dist4[(size_t)row * 4 + 2];
        const float4 d = dist4[(size_t)row * 4 + 3];

        // hinge = relu(1 - x)
        const float h0 = fmaxf(1.0f - a.x, 0.0f);
        const float h1 = fmaxf(1.0f - a.y, 0.0f);
        float hs = h0 + h1
                 + fmaxf(1.0f - a.z, 0.0f) + fmaxf(1.0f - a.w, 0.0f)
                 + fmaxf(1.0f - b.x, 0.0f) + fmaxf(1.0f - b.y, 0.0f)
                 + fmaxf(1.0f - b.z, 0.0f) + fmaxf(1.0f - b.w, 0.0f)
                 + fmaxf(1.0f - c.x, 0.0f) + fmaxf(1.0f - c.y, 0.0f)
                 + fmaxf(1.0f - c.z, 0.0f) + fmaxf(1.0f - c.w, 0.0f)
                 + fmaxf(1.0f - d.x, 0.0f) + fmaxf(1.0f - d.y, 0.0f)
                 + fmaxf(1.0f - d.z, 0.0f) + fmaxf(1.0f - d.w, 0.0f);

        const int dl = doctor[row];
        const int rl = real_l[row];

        const float loss_control   = a.x + hs - h0;
        const float loss_parkinson = a.y + hs - h1;
        const float loss_unknown   = (rl == 0) ? h1 : h0;

        const float loss = (dl == 0) ? loss_control
                         : (dl == 1) ? loss_parkinson
                                     : loss_unknown;
        acc += loss;
    }

    // warp reduce
    #pragma unroll
    for (int off = 16; off > 0; off >>= 1)
        acc += __shfl_xor_sync(0xFFFFFFFFu, acc, off);

    // block reduce
    __shared__ float warp_sums[THREADS / 32];
    const int lane = threadIdx.x & 31;
    const int wid  = threadIdx.x >> 5;
    if (lane == 0) warp_sums[wid] = acc;
    __syncthreads();

    if (wid == 0) {
        float v = (lane < THREADS / 32) ? warp_sums[lane] : 0.0f;
        #pragma unroll
        for (int off = 16; off > 0; off >>= 1)
            v += __shfl_xor_sync(0xFFFFFFFFu, v, off);
        if (lane == 0)
            atomicAdd(out, v * inv_B);
    }
}

extern "C" void kernel_launch(void* const* d_in, const int* in_sizes, int n_in,
                              void* d_out, int out_size)
{
    const float4* dist4  = (const float4*)d_in[0];
    const int*    doctor = (const int*)d_in[1];
    const int*    real_l = (const int*)d_in[2];
    float*        out    = (float*)d_out;

    const int B = in_sizes[1];           // label count = number of rows
    const float inv_B = 1.0f / (float)B;

    zero_out_kernel<<<1, 32>>>(out);

    const int blocks = 2048;             // 8 rows/thread at B=4M
    mlloss_kernel<<<blocks, THREADS>>>(dist4, doctor, real_l, out, B, inv_B);
}